// round 6
// baseline (speedup 1.0000x reference)
#include <cuda_runtime.h>
#include <cuda_fp16.h>
#include <cstdint>
#include <math.h>

// ---------------------------------------------------------------------------
// Luong 'general' attention, B=16, T=S=E=D=1024.
// Out: [h_tilde | attn_weights | attn_energies] fp32.
// All GEMMs: mma.sync m16n8k16 fp16 3-term hi/lo split, fp32 acc.
// Block tile 128x256, 8 warps (2x4), warp tile 64x64, K-chunk 64,
// cp.async double-buffered. MMA:LDSM ratio 6 (smem-port no longer binding).
// ---------------------------------------------------------------------------

typedef __half hf;

#define BATCH 16
#define TDIM 1024
#define SDIM 1024
#define EDIM 1024
#define DDIM 1024
#define NBT (16 * 1024 * 1024)

__device__ __align__(256) hf g_enc_h[NBT],  g_enc_l[NBT];
__device__ __align__(256) hf g_encT_h[NBT], g_encT_l[NBT];
__device__ __align__(256) hf g_hid_h[NBT],  g_hid_l[NBT];
__device__ __align__(256) hf g_proj_h[NBT], g_proj_l[NBT];
__device__ __align__(256) hf g_wts_h[NBT],  g_wts_l[NBT];
__device__ __align__(256) hf g_ctx_h[NBT],  g_ctx_l[NBT];
__device__ __align__(256) hf g_wa_h[1024 * 1024], g_wa_l[1024 * 1024];
__device__ __align__(256) hf g_wo_h[1024 * 2048], g_wo_l[1024 * 2048];

// ------------------------------ PTX helpers --------------------------------
__device__ __forceinline__ uint32_t smem_u32(const void* p) {
    uint32_t a;
    asm("{ .reg .u64 t; cvta.to.shared.u64 t, %1; cvt.u32.u64 %0, t; }"
        : "=r"(a) : "l"(p));
    return a;
}
__device__ __forceinline__ uint32_t swz(uint32_t off) {  // SW128: 128B rows
    return off ^ ((off >> 3) & 0x70);
}

#define CP_ASYNC16(saddr, gptr) \
    asm volatile("cp.async.cg.shared.global [%0], [%1], 16;" \
                 :: "r"(saddr), "l"(gptr) : "memory")
#define CP_COMMIT() asm volatile("cp.async.commit_group;" ::: "memory")
#define CP_WAIT0()  asm volatile("cp.async.wait_group 0;" ::: "memory")

#define LDSM4(r0, r1, r2, r3, addr) \
    asm volatile("ldmatrix.sync.aligned.m8n8.x4.shared.b16 {%0,%1,%2,%3}, [%4];" \
                 : "=r"(r0), "=r"(r1), "=r"(r2), "=r"(r3) : "r"(addr))

#define MMA16816(d, a, b0, b1) \
    asm volatile("mma.sync.aligned.m16n8k16.row.col.f32.f16.f16.f32 " \
                 "{%0,%1,%2,%3}, {%4,%5,%6,%7}, {%8,%9}, {%0,%1,%2,%3};" \
                 : "+f"((d)[0]), "+f"((d)[1]), "+f"((d)[2]), "+f"((d)[3]) \
                 : "r"((a)[0]), "r"((a)[1]), "r"((a)[2]), "r"((a)[3]), \
                   "r"(b0), "r"(b1))

__device__ __forceinline__ uint32_t packh(hf a, hf b) {
    __half2 t; t.x = a; t.y = b;
    return *reinterpret_cast<uint32_t*>(&t);
}

// ------------------------------ GEMM kernel --------------------------------
// Buffer: [Ah 16K][Al 16K][Bh 32K][Bl 32K] = 96KB, double-buffered = 192KB.
#define BUF_BYTES 98304
#define SMEM_BYTES (2 * BUF_BYTES)

__device__ __forceinline__ void stage_loads(
    uint32_t sbuf, const hf* pah, const hf* pal, const hf* pbh, const hf* pbl,
    int bm, int bn, int ldA, int ldB, int k0, int tid)
{
    // A: 128 rows x 128B (hi+lo)
    #pragma unroll
    for (int j = 0; j < 4; ++j) {
        const int idx = tid + j * 256;            // 0..1023
        const int r = idx >> 3, g = idx & 7;
        const uint32_t so = swz((uint32_t)(r * 128 + g * 16));
        const size_t ao = (size_t)(bm + r) * ldA + k0 + g * 8;
        CP_ASYNC16(sbuf + so,         pah + ao);
        CP_ASYNC16(sbuf + 16384 + so, pal + ao);
    }
    // B: 256 rows x 128B (hi+lo)
    #pragma unroll
    for (int j = 0; j < 8; ++j) {
        const int idx = tid + j * 256;            // 0..2047
        const int r = idx >> 3, g = idx & 7;
        const uint32_t so = swz((uint32_t)(r * 128 + g * 16));
        const size_t bo = (size_t)(bn + r) * ldB + k0 + g * 8;
        CP_ASYNC16(sbuf + 32768 + so, pbh + bo);
        CP_ASYNC16(sbuf + 65536 + so, pbl + bo);
    }
}

// EPI: 0 = f32 store, 1 = bias + split, 2 = split, 3 = tanh f32
template<int EPI>
__global__ void __launch_bounds__(256, 1)
mma_gemm(const hf* __restrict__ Ah, const hf* __restrict__ Al,
         const hf* __restrict__ Bh, const hf* __restrict__ Bl,
         const hf* __restrict__ A2h, const hf* __restrict__ A2l,
         const hf* __restrict__ B2h, const hf* __restrict__ B2l,
         const float* __restrict__ bias,
         float* __restrict__ Cf, hf* __restrict__ Ch, hf* __restrict__ Cl,
         int NC1, int NC2, int lda, int ldb, int lda2, int ldb2, int ldc,
         long long sA, long long sB, long long sC)
{
    extern __shared__ char smem[];
    const uint32_t sb = smem_u32(smem);
    const int tid  = threadIdx.x;
    const int wid  = tid >> 5;
    const int lane = tid & 31;
    const long long z = blockIdx.z;
    Ah += z * sA; Al += z * sA; Bh += z * sB; Bl += z * sB;
    if (EPI == 0 || EPI == 3) Cf += z * sC;
    else { Ch += z * sC; Cl += z * sC; }

    const int bm = blockIdx.y * 128;
    const int bn = blockIdx.x * 256;
    const int wm = (wid >> 2) * 64;     // warp m offset (0 or 64)
    const int wn = (wid & 3) * 64;      // warp n offset (0/64/128/192)

    float acc[4][8][4];
    #pragma unroll
    for (int i = 0; i < 4; i++)
        #pragma unroll
        for (int j = 0; j < 8; j++)
            #pragma unroll
            for (int q = 0; q < 4; q++) acc[i][j][q] = 0.0f;

    const int NC = NC1 + NC2;

    stage_loads(sb, Ah, Al, Bh, Bl, bm, bn, lda, ldb, 0, tid);
    CP_COMMIT();

    for (int c = 0; c < NC; ++c) {
        const int buf = c & 1;
        CP_WAIT0();
        __syncthreads();

        if (c + 1 < NC) {
            const int cn = c + 1;
            if (cn < NC1)
                stage_loads(sb + (buf ^ 1) * BUF_BYTES, Ah, Al, Bh, Bl,
                            bm, bn, lda, ldb, cn * 64, tid);
            else
                stage_loads(sb + (buf ^ 1) * BUF_BYTES, A2h, A2l, B2h, B2l,
                            bm, bn, lda2, ldb2, (cn - NC1) * 64, tid);
            CP_COMMIT();
        }

        const uint32_t ab = sb + buf * BUF_BYTES;
        const uint32_t bb = ab + 32768;

        #pragma unroll
        for (int ks = 0; ks < 4; ++ks) {
            uint32_t ah[4][4], al[4][4], bh[4][4], bl[4][4];
            const int arow = wm + (lane & 15);
            const int akb  = ks * 32 + ((lane >> 4) << 4);
            #pragma unroll
            for (int mi = 0; mi < 4; ++mi) {
                const uint32_t ad = ab + swz((uint32_t)((arow + mi * 16) * 128 + akb));
                LDSM4(ah[mi][0], ah[mi][1], ah[mi][2], ah[mi][3], ad);
                LDSM4(al[mi][0], al[mi][1], al[mi][2], al[mi][3], ad + 16384);
            }
            const int brow = wn + (lane & 7) + ((lane >> 4) << 3);
            const int bkb  = ks * 32 + (((lane >> 3) & 1) << 4);
            #pragma unroll
            for (int nj = 0; nj < 4; ++nj) {
                const uint32_t bd = bb + swz((uint32_t)((brow + nj * 16) * 128 + bkb));
                LDSM4(bh[nj][0], bh[nj][1], bh[nj][2], bh[nj][3], bd);
                LDSM4(bl[nj][0], bl[nj][1], bl[nj][2], bl[nj][3], bd + 32768);
            }
            #pragma unroll
            for (int mi = 0; mi < 4; ++mi)
                #pragma unroll
                for (int o = 0; o < 8; ++o) {
                    const uint32_t b0h = bh[o >> 1][(o & 1) * 2];
                    const uint32_t b1h = bh[o >> 1][(o & 1) * 2 + 1];
                    const uint32_t b0l = bl[o >> 1][(o & 1) * 2];
                    const uint32_t b1l = bl[o >> 1][(o & 1) * 2 + 1];
                    MMA16816(acc[mi][o], ah[mi], b0h, b1h);
                    MMA16816(acc[mi][o], ah[mi], b0l, b1l);
                    MMA16816(acc[mi][o], al[mi], b0h, b1h);
                }
        }
    }

    // ------------------------------- epilogue ------------------------------
    const int rbase = bm + wm + (lane >> 2);
    const int cbase = bn + wn + (lane & 3) * 2;
    #pragma unroll
    for (int mi = 0; mi < 4; ++mi) {
        #pragma unroll
        for (int o = 0; o < 8; ++o) {
            const long long r0 = rbase + mi * 16;
            const int col = cbase + o * 8;
            float c0 = acc[mi][o][0], c1 = acc[mi][o][1];
            float c2 = acc[mi][o][2], c3 = acc[mi][o][3];
            if (EPI == 1) {
                const float bv0 = __ldg(bias + col), bv1 = __ldg(bias + col + 1);
                c0 += bv0; c1 += bv1; c2 += bv0; c3 += bv1;
            }
            if (EPI == 3) {
                c0 = tanhf(c0); c1 = tanhf(c1); c2 = tanhf(c2); c3 = tanhf(c3);
            }
            if (EPI == 0 || EPI == 3) {
                *(float2*)(Cf + r0 * ldc + col)       = make_float2(c0, c1);
                *(float2*)(Cf + (r0 + 8) * ldc + col) = make_float2(c2, c3);
            } else {
                hf h0 = __float2half_rn(c0), h1 = __float2half_rn(c1);
                hf h2 = __float2half_rn(c2), h3 = __float2half_rn(c3);
                hf l0 = __float2half_rn(c0 - __half2float(h0));
                hf l1 = __float2half_rn(c1 - __half2float(h1));
                hf l2 = __float2half_rn(c2 - __half2float(h2));
                hf l3 = __float2half_rn(c3 - __half2float(h3));
                *(uint32_t*)(Ch + r0 * ldc + col)       = packh(h0, h1);
                *(uint32_t*)(Ch + (r0 + 8) * ldc + col) = packh(h2, h3);
                *(uint32_t*)(Cl + r0 * ldc + col)       = packh(l0, l1);
                *(uint32_t*)(Cl + (r0 + 8) * ldc + col) = packh(l2, l3);
            }
        }
    }
}

// --------------------------- auxiliary kernels -----------------------------
__global__ void __launch_bounds__(256)
split_k(const float4* __restrict__ x, uint2* __restrict__ h,
        uint2* __restrict__ l, int n4)
{
    const int i = blockIdx.x * 256 + threadIdx.x;
    if (i >= n4) return;
    const float4 v = x[i];
    hf h0 = __float2half_rn(v.x), h1 = __float2half_rn(v.y);
    hf h2 = __float2half_rn(v.z), h3 = __float2half_rn(v.w);
    hf l0 = __float2half_rn(v.x - __half2float(h0));
    hf l1 = __float2half_rn(v.y - __half2float(h1));
    hf l2 = __float2half_rn(v.z - __half2float(h2));
    hf l3 = __float2half_rn(v.w - __half2float(h3));
    h[i] = make_uint2(packh(h0, h1), packh(h2, h3));
    l[i] = make_uint2(packh(l0, l1), packh(l2, l3));
}

// encT[b][e][s] = enc[b][s][e], split hi/lo fp16
__global__ void __launch_bounds__(256)
tsplit_k(const float* __restrict__ x, hf* __restrict__ th, hf* __restrict__ tl)
{
    __shared__ float t[32][33];
    const long long z = blockIdx.z;
    const float* xp = x + z * (long long)SDIM * EDIM;
    hf* hp = th + z * (long long)EDIM * SDIM;
    hf* lp = tl + z * (long long)EDIM * SDIM;
    const int e0 = blockIdx.x * 32, s0 = blockIdx.y * 32;
    const int tx = threadIdx.x & 31, ty = threadIdx.x >> 5;
    #pragma unroll
    for (int j = 0; j < 4; ++j)
        t[ty + 8 * j][tx] = xp[(long long)(s0 + ty + 8 * j) * EDIM + e0 + tx];
    __syncthreads();
    #pragma unroll
    for (int j = 0; j < 4; ++j) {
        const float v = t[tx][ty + 8 * j];
        const hf h = __float2half_rn(v);
        const long long o = (long long)(e0 + ty + 8 * j) * SDIM + s0 + tx;
        hp[o] = h;
        lp[o] = __float2half_rn(v - __half2float(h));
    }
}

// row softmax (S=1024): fp32 weights out + fp16 hi/lo split
__global__ void __launch_bounds__(256)
softmax_sp(const float* __restrict__ E, float* __restrict__ W,
           hf* __restrict__ Wh, hf* __restrict__ Wl)
{
    __shared__ float red[8];
    const long long row = blockIdx.x;
    const float4* e = (const float4*)(E + (row << 10));
    float4* w = (float4*)(W + (row << 10));
    const int t = threadIdx.x;

    float4 v = e[t];
    float m = fmaxf(fmaxf(v.x, v.y), fmaxf(v.z, v.w));
    #pragma unroll
    for (int o = 16; o; o >>= 1) m = fmaxf(m, __shfl_xor_sync(0xffffffffu, m, o));
    if ((t & 31) == 0) red[t >> 5] = m;
    __syncthreads();
    m = red[0];
    #pragma unroll
    for (int i = 1; i < 8; i++) m = fmaxf(m, red[i]);
    __syncthreads();

    float e0 = expf(v.x - m), e1 = expf(v.y - m);
    float e2 = expf(v.z - m), e3 = expf(v.w - m);
    float s = e0 + e1 + e2 + e3;
    #pragma unroll
    for (int o = 16; o; o >>= 1) s += __shfl_xor_sync(0xffffffffu, s, o);
    if ((t & 31) == 0) red[t >> 5] = s;
    __syncthreads();
    s = red[0] + red[1] + red[2] + red[3] + red[4] + red[5] + red[6] + red[7];

    const float inv = 1.0f / s;
    const float w0 = e0 * inv, w1 = e1 * inv, w2 = e2 * inv, w3 = e3 * inv;
    w[t] = make_float4(w0, w1, w2, w3);

    hf h0 = __float2half_rn(w0), h1 = __float2half_rn(w1);
    hf h2 = __float2half_rn(w2), h3 = __float2half_rn(w3);
    hf l0 = __float2half_rn(w0 - __half2float(h0));
    hf l1 = __float2half_rn(w1 - __half2float(h1));
    hf l2 = __float2half_rn(w2 - __half2float(h2));
    hf l3 = __float2half_rn(w3 - __half2float(h3));
    ((uint2*)(Wh + (row << 10)))[t] = make_uint2(packh(h0, h1), packh(h2, h3));
    ((uint2*)(Wl + (row << 10)))[t] = make_uint2(packh(l0, l1), packh(l2, l3));
}

// -------------------------------- launcher ---------------------------------
extern "C" void kernel_launch(void* const* d_in, const int* in_sizes, int n_in,
                              void* d_out, int out_size)
{
    const float* hidden = (const float*)d_in[0];
    const float* enc    = (const float*)d_in[1];
    const float* Wa     = (const float*)d_in[2];
    const float* ba     = (const float*)d_in[3];
    const float* Wo     = (const float*)d_in[4];

    float* out = (float*)d_out;
    const long long SZ = (long long)NBT;
    float* htilde = out;
    float* wts    = out + SZ;
    float* enrg   = out + 2 * SZ;

    hf *enc_h, *enc_l, *encT_h, *encT_l, *hid_h, *hid_l, *proj_h, *proj_l;
    hf *wts_h, *wts_l, *ctx_h, *ctx_l, *wa_h, *wa_l, *wo_h, *wo_l;
    cudaGetSymbolAddress((void**)&enc_h,  g_enc_h);  cudaGetSymbolAddress((void**)&enc_l,  g_enc_l);
    cudaGetSymbolAddress((void**)&encT_h, g_encT_h); cudaGetSymbolAddress((void**)&encT_l, g_encT_l);
    cudaGetSymbolAddress((void**)&hid_h,  g_hid_h);  cudaGetSymbolAddress((void**)&hid_l,  g_hid_l);
    cudaGetSymbolAddress((void**)&proj_h, g_proj_h); cudaGetSymbolAddress((void**)&proj_l, g_proj_l);
    cudaGetSymbolAddress((void**)&wts_h,  g_wts_h);  cudaGetSymbolAddress((void**)&wts_l,  g_wts_l);
    cudaGetSymbolAddress((void**)&ctx_h,  g_ctx_h);  cudaGetSymbolAddress((void**)&ctx_l,  g_ctx_l);
    cudaGetSymbolAddress((void**)&wa_h,   g_wa_h);   cudaGetSymbolAddress((void**)&wa_l,   g_wa_l);
    cudaGetSymbolAddress((void**)&wo_h,   g_wo_h);   cudaGetSymbolAddress((void**)&wo_l,   g_wo_l);

    cudaFuncSetAttribute(mma_gemm<0>, cudaFuncAttributeMaxDynamicSharedMemorySize, SMEM_BYTES);
    cudaFuncSetAttribute(mma_gemm<1>, cudaFuncAttributeMaxDynamicSharedMemorySize, SMEM_BYTES);
    cudaFuncSetAttribute(mma_gemm<2>, cudaFuncAttributeMaxDynamicSharedMemorySize, SMEM_BYTES);
    cudaFuncSetAttribute(mma_gemm<3>, cudaFuncAttributeMaxDynamicSharedMemorySize, SMEM_BYTES);

    // operand splits
    split_k<<<NBT / 4 / 256, 256>>>((const float4*)enc,    (uint2*)enc_h, (uint2*)enc_l, NBT / 4);
    split_k<<<NBT / 4 / 256, 256>>>((const float4*)hidden, (uint2*)hid_h, (uint2*)hid_l, NBT / 4);
    split_k<<<1024, 256>>>((const float4*)Wa, (uint2*)wa_h, (uint2*)wa_l, 1024 * 1024 / 4);
    split_k<<<2048, 256>>>((const float4*)Wo, (uint2*)wo_h, (uint2*)wo_l, 1024 * 2048 / 4);
    tsplit_k<<<dim3(EDIM / 32, SDIM / 32, BATCH), 256>>>(enc, encT_h, encT_l);

    // Stage 1: proj = enc @ Wa^T + ba -> split   (M=16384, N=1024, K=1024)
    mma_gemm<1><<<dim3(DDIM / 256, (BATCH * SDIM) / 128, 1), 256, SMEM_BYTES>>>(
        enc_h, enc_l, wa_h, wa_l, nullptr, nullptr, nullptr, nullptr, ba,
        nullptr, proj_h, proj_l, EDIM / 64, 0, EDIM, EDIM, 0, 0, DDIM, 0, 0, 0);

    // Stage 2: energies = hidden @ proj^T (batched) -> fp32
    mma_gemm<0><<<dim3(SDIM / 256, TDIM / 128, BATCH), 256, SMEM_BYTES>>>(
        hid_h, hid_l, proj_h, proj_l, nullptr, nullptr, nullptr, nullptr, nullptr,
        enrg, nullptr, nullptr, DDIM / 64, 0, DDIM, DDIM, 0, 0, SDIM,
        (long long)TDIM * DDIM, (long long)SDIM * DDIM, (long long)TDIM * SDIM);

    // Stage 3: softmax -> fp32 weights + fp16 split
    softmax_sp<<<BATCH * TDIM, 256>>>(enrg, wts, wts_h, wts_l);

    // Stage 4: ctx = weights @ encT^T (batched) -> split
    mma_gemm<2><<<dim3(EDIM / 256, TDIM / 128, BATCH), 256, SMEM_BYTES>>>(
        wts_h, wts_l, encT_h, encT_l, nullptr, nullptr, nullptr, nullptr, nullptr,
        nullptr, ctx_h, ctx_l, SDIM / 64, 0, SDIM, SDIM, 0, 0, EDIM,
        (long long)TDIM * SDIM, (long long)EDIM * SDIM, (long long)TDIM * EDIM);

    // Stage 5: h_tilde = tanh(ctx @ Wo[:, :E]^T + hidden @ Wo[:, E:]^T)
    mma_gemm<3><<<dim3(DDIM / 256, (BATCH * TDIM) / 128, 1), 256, SMEM_BYTES>>>(
        ctx_h, ctx_l, wo_h, wo_l, hid_h, hid_l, wo_h + EDIM, wo_l + EDIM, nullptr,
        htilde, nullptr, nullptr, EDIM / 64, DDIM / 64,
        EDIM, EDIM + DDIM, DDIM, EDIM + DDIM, DDIM, 0, 0, 0);
}

// round 7
// speedup vs baseline: 1.2560x; 1.2560x over previous
#include <cuda_runtime.h>
#include <cuda_fp16.h>
#include <cstdint>
#include <math.h>

// ---------------------------------------------------------------------------
// Luong 'general' attention, B=16, T=S=E=D=1024.
// Out: [h_tilde | attn_weights | attn_energies] fp32.
// GEMMs: mma.sync m16n8k16 fp16 hi/lo split, fp32 acc.
//   Stages 1-2 (proj, energies): 3-term split (fp32-equivalent, softmax-safe)
//   Stages 4-5 (ctx, h_tilde):   2-term split (1.4e-4 rel, 7x under gate)
// Block 128x128, 8 warps (2x4), warp tile 64x32, K-chunk 64,
// 3-stage cp.async pipeline (wait_group 1).
// ---------------------------------------------------------------------------

typedef __half hf;

#define BATCH 16
#define TDIM 1024
#define SDIM 1024
#define EDIM 1024
#define DDIM 1024
#define NBT (16 * 1024 * 1024)

__device__ __align__(256) hf g_enc_h[NBT],  g_enc_l[NBT];
__device__ __align__(256) hf g_encT_h[NBT], g_encT_l[NBT];
__device__ __align__(256) hf g_hid_h[NBT],  g_hid_l[NBT];
__device__ __align__(256) hf g_proj_h[NBT], g_proj_l[NBT];
__device__ __align__(256) hf g_wts_h[NBT],  g_wts_l[NBT];
__device__ __align__(256) hf g_ctx_h[NBT],  g_ctx_l[NBT];
__device__ __align__(256) hf g_wa_h[1024 * 1024], g_wa_l[1024 * 1024];
__device__ __align__(256) hf g_wo_h[1024 * 2048], g_wo_l[1024 * 2048];

// ------------------------------ PTX helpers --------------------------------
__device__ __forceinline__ uint32_t smem_u32(const void* p) {
    uint32_t a;
    asm("{ .reg .u64 t; cvta.to.shared.u64 t, %1; cvt.u32.u64 %0, t; }"
        : "=r"(a) : "l"(p));
    return a;
}
__device__ __forceinline__ uint32_t swz(uint32_t off) {  // SW128: 128B rows
    return off ^ ((off >> 3) & 0x70);
}

#define CP_ASYNC16(saddr, gptr) \
    asm volatile("cp.async.cg.shared.global [%0], [%1], 16;" \
                 :: "r"(saddr), "l"(gptr) : "memory")
#define CP_COMMIT() asm volatile("cp.async.commit_group;" ::: "memory")
#define CP_WAITN(n) asm volatile("cp.async.wait_group %0;" :: "n"(n) : "memory")

#define LDSM4(r0, r1, r2, r3, addr) \
    asm volatile("ldmatrix.sync.aligned.m8n8.x4.shared.b16 {%0,%1,%2,%3}, [%4];" \
                 : "=r"(r0), "=r"(r1), "=r"(r2), "=r"(r3) : "r"(addr))

#define MMA16816(d, a, b0, b1) \
    asm volatile("mma.sync.aligned.m16n8k16.row.col.f32.f16.f16.f32 " \
                 "{%0,%1,%2,%3}, {%4,%5,%6,%7}, {%8,%9}, {%0,%1,%2,%3};" \
                 : "+f"((d)[0]), "+f"((d)[1]), "+f"((d)[2]), "+f"((d)[3]) \
                 : "r"((a)[0]), "r"((a)[1]), "r"((a)[2]), "r"((a)[3]), \
                   "r"(b0), "r"(b1))

__device__ __forceinline__ uint32_t packh(hf a, hf b) {
    __half2 t; t.x = a; t.y = b;
    return *reinterpret_cast<uint32_t*>(&t);
}

// ------------------------------ GEMM kernel --------------------------------
// Buffer (64KB): [Ah 16K][Al 16K][Bh 16K][Bl 16K], 3-stage pipeline = 192KB.
#define BUF_BYTES 65536
#define SMEM_BYTES (3 * BUF_BYTES)

template<int NT>
__device__ __forceinline__ void stage_loads(
    uint32_t sbuf, const hf* pah, const hf* pal, const hf* pbh, const hf* pbl,
    int bm, int bn, int ldA, int ldB, int k0, int tid)
{
    #pragma unroll
    for (int j = 0; j < 4; ++j) {
        const int idx = tid + j * 256;
        const int r = idx >> 3, g = idx & 7;
        const uint32_t so = swz((uint32_t)(r * 128 + g * 16));
        const size_t ao = (size_t)(bm + r) * ldA + k0 + g * 8;
        const size_t bo = (size_t)(bn + r) * ldB + k0 + g * 8;
        CP_ASYNC16(sbuf + so, pah + ao);
        if (NT == 3) CP_ASYNC16(sbuf + 16384 + so, pal + ao);
        CP_ASYNC16(sbuf + 32768 + so, pbh + bo);
        CP_ASYNC16(sbuf + 49152 + so, pbl + bo);
    }
}

// EPI: 0 = f32 store, 1 = bias + split, 2 = split, 3 = tanh f32
// NT : 3 = ah*bh + ah*bl + al*bh ; 2 = ah*bh + ah*bl (A-lo never loaded)
template<int EPI, int NT>
__global__ void __launch_bounds__(256, 1)
mma_gemm(const hf* __restrict__ Ah, const hf* __restrict__ Al,
         const hf* __restrict__ Bh, const hf* __restrict__ Bl,
         const hf* __restrict__ A2h, const hf* __restrict__ A2l,
         const hf* __restrict__ B2h, const hf* __restrict__ B2l,
         const float* __restrict__ bias,
         float* __restrict__ Cf, hf* __restrict__ Ch, hf* __restrict__ Cl,
         int NC1, int NC2, int lda, int ldb, int lda2, int ldb2, int ldc,
         long long sA, long long sB, long long sC)
{
    extern __shared__ char smem[];
    const uint32_t sb = smem_u32(smem);
    const int tid  = threadIdx.x;
    const int wid  = tid >> 5;
    const int lane = tid & 31;
    const long long z = blockIdx.z;
    Ah += z * sA; Al += z * sA; Bh += z * sB; Bl += z * sB;
    if (EPI == 0 || EPI == 3) Cf += z * sC;
    else { Ch += z * sC; Cl += z * sC; }

    const int bm = blockIdx.y * 128;
    const int bn = blockIdx.x * 128;
    const int wm = (wid >> 2) * 64;     // warp m offset (0 or 64)
    const int wn = (wid & 3) * 32;      // warp n offset (0/32/64/96)

    float acc[4][4][4];
    #pragma unroll
    for (int i = 0; i < 4; i++)
        #pragma unroll
        for (int j = 0; j < 4; j++)
            #pragma unroll
            for (int q = 0; q < 4; q++) acc[i][j][q] = 0.0f;

    const int NC = NC1 + NC2;

    // prologue: chunks 0 and 1
    stage_loads<NT>(sb, Ah, Al, Bh, Bl, bm, bn, lda, ldb, 0, tid);
    CP_COMMIT();
    if (NC > 1) {
        if (1 < NC1) stage_loads<NT>(sb + BUF_BYTES, Ah, Al, Bh, Bl, bm, bn, lda, ldb, 64, tid);
        else         stage_loads<NT>(sb + BUF_BYTES, A2h, A2l, B2h, B2l, bm, bn, lda2, ldb2, 0, tid);
    }
    CP_COMMIT();

    for (int c = 0; c < NC; ++c) {
        CP_WAITN(1);
        __syncthreads();

        if (c + 2 < NC) {
            const int cn = c + 2;
            const uint32_t nb = sb + (uint32_t)(cn % 3) * BUF_BYTES;
            if (cn < NC1)
                stage_loads<NT>(nb, Ah, Al, Bh, Bl, bm, bn, lda, ldb, cn * 64, tid);
            else
                stage_loads<NT>(nb, A2h, A2l, B2h, B2l, bm, bn, lda2, ldb2, (cn - NC1) * 64, tid);
            CP_COMMIT();
        }

        const uint32_t ab = sb + (uint32_t)(c % 3) * BUF_BYTES;
        const uint32_t bb = ab + 32768;

        #pragma unroll
        for (int ks = 0; ks < 4; ++ks) {
            uint32_t ah[4][4], al[4][4], bh[2][4], bl[2][4];
            const int arow = wm + (lane & 15);
            const int akb  = ks * 32 + ((lane >> 4) << 4);
            #pragma unroll
            for (int mi = 0; mi < 4; ++mi) {
                const uint32_t ad = ab + swz((uint32_t)((arow + mi * 16) * 128 + akb));
                LDSM4(ah[mi][0], ah[mi][1], ah[mi][2], ah[mi][3], ad);
                if (NT == 3) LDSM4(al[mi][0], al[mi][1], al[mi][2], al[mi][3], ad + 16384);
            }
            const int brow = wn + (lane & 7) + ((lane >> 4) << 3);
            const int bkb  = ks * 32 + (((lane >> 3) & 1) << 4);
            #pragma unroll
            for (int nj = 0; nj < 2; ++nj) {
                const uint32_t bd = bb + swz((uint32_t)((brow + nj * 16) * 128 + bkb));
                LDSM4(bh[nj][0], bh[nj][1], bh[nj][2], bh[nj][3], bd);
                LDSM4(bl[nj][0], bl[nj][1], bl[nj][2], bl[nj][3], bd + 16384);
            }
            #pragma unroll
            for (int mi = 0; mi < 4; ++mi)
                #pragma unroll
                for (int o = 0; o < 4; ++o) {
                    const uint32_t b0h = bh[o >> 1][(o & 1) * 2];
                    const uint32_t b1h = bh[o >> 1][(o & 1) * 2 + 1];
                    const uint32_t b0l = bl[o >> 1][(o & 1) * 2];
                    const uint32_t b1l = bl[o >> 1][(o & 1) * 2 + 1];
                    MMA16816(acc[mi][o], ah[mi], b0h, b1h);
                    MMA16816(acc[mi][o], ah[mi], b0l, b1l);
                    if (NT == 3) MMA16816(acc[mi][o], al[mi], b0h, b1h);
                }
        }
    }

    // ------------------------------- epilogue ------------------------------
    const int rbase = bm + wm + (lane >> 2);
    const int cbase = bn + wn + (lane & 3) * 2;
    #pragma unroll
    for (int mi = 0; mi < 4; ++mi) {
        #pragma unroll
        for (int o = 0; o < 4; ++o) {
            const long long r0 = rbase + mi * 16;
            const int col = cbase + o * 8;
            float c0 = acc[mi][o][0], c1 = acc[mi][o][1];
            float c2 = acc[mi][o][2], c3 = acc[mi][o][3];
            if (EPI == 1) {
                const float bv0 = __ldg(bias + col), bv1 = __ldg(bias + col + 1);
                c0 += bv0; c1 += bv1; c2 += bv0; c3 += bv1;
            }
            if (EPI == 3) {
                c0 = tanhf(c0); c1 = tanhf(c1); c2 = tanhf(c2); c3 = tanhf(c3);
            }
            if (EPI == 0 || EPI == 3) {
                *(float2*)(Cf + r0 * ldc + col)       = make_float2(c0, c1);
                *(float2*)(Cf + (r0 + 8) * ldc + col) = make_float2(c2, c3);
            } else {
                hf h0 = __float2half_rn(c0), h1 = __float2half_rn(c1);
                hf h2 = __float2half_rn(c2), h3 = __float2half_rn(c3);
                hf l0 = __float2half_rn(c0 - __half2float(h0));
                hf l1 = __float2half_rn(c1 - __half2float(h1));
                hf l2 = __float2half_rn(c2 - __half2float(h2));
                hf l3 = __float2half_rn(c3 - __half2float(h3));
                *(uint32_t*)(Ch + r0 * ldc + col)       = packh(h0, h1);
                *(uint32_t*)(Ch + (r0 + 8) * ldc + col) = packh(h2, h3);
                *(uint32_t*)(Cl + r0 * ldc + col)       = packh(l0, l1);
                *(uint32_t*)(Cl + (r0 + 8) * ldc + col) = packh(l2, l3);
            }
        }
    }
}

// --------------------------- auxiliary kernels -----------------------------
__global__ void __launch_bounds__(256)
split_k(const float4* __restrict__ x, uint2* __restrict__ h,
        uint2* __restrict__ l, int n4)
{
    const int i = blockIdx.x * 256 + threadIdx.x;
    if (i >= n4) return;
    const float4 v = x[i];
    hf h0 = __float2half_rn(v.x), h1 = __float2half_rn(v.y);
    hf h2 = __float2half_rn(v.z), h3 = __float2half_rn(v.w);
    hf l0 = __float2half_rn(v.x - __half2float(h0));
    hf l1 = __float2half_rn(v.y - __half2float(h1));
    hf l2 = __float2half_rn(v.z - __half2float(h2));
    hf l3 = __float2half_rn(v.w - __half2float(h3));
    h[i] = make_uint2(packh(h0, h1), packh(h2, h3));
    l[i] = make_uint2(packh(l0, l1), packh(l2, l3));
}

// encT[b][e][s] = enc[b][s][e], split hi/lo fp16
__global__ void __launch_bounds__(256)
tsplit_k(const float* __restrict__ x, hf* __restrict__ th, hf* __restrict__ tl)
{
    __shared__ float t[32][33];
    const long long z = blockIdx.z;
    const float* xp = x + z * (long long)SDIM * EDIM;
    hf* hp = th + z * (long long)EDIM * SDIM;
    hf* lp = tl + z * (long long)EDIM * SDIM;
    const int e0 = blockIdx.x * 32, s0 = blockIdx.y * 32;
    const int tx = threadIdx.x & 31, ty = threadIdx.x >> 5;
    #pragma unroll
    for (int j = 0; j < 4; ++j)
        t[ty + 8 * j][tx] = xp[(long long)(s0 + ty + 8 * j) * EDIM + e0 + tx];
    __syncthreads();
    #pragma unroll
    for (int j = 0; j < 4; ++j) {
        const float v = t[tx][ty + 8 * j];
        const hf h = __float2half_rn(v);
        const long long o = (long long)(e0 + ty + 8 * j) * SDIM + s0 + tx;
        hp[o] = h;
        lp[o] = __float2half_rn(v - __half2float(h));
    }
}

// row softmax (S=1024): fp32 weights out + fp16 hi/lo split
__global__ void __launch_bounds__(256)
softmax_sp(const float* __restrict__ E, float* __restrict__ W,
           hf* __restrict__ Wh, hf* __restrict__ Wl)
{
    __shared__ float red[8];
    const long long row = blockIdx.x;
    const float4* e = (const float4*)(E + (row << 10));
    float4* w = (float4*)(W + (row << 10));
    const int t = threadIdx.x;

    float4 v = e[t];
    float m = fmaxf(fmaxf(v.x, v.y), fmaxf(v.z, v.w));
    #pragma unroll
    for (int o = 16; o; o >>= 1) m = fmaxf(m, __shfl_xor_sync(0xffffffffu, m, o));
    if ((t & 31) == 0) red[t >> 5] = m;
    __syncthreads();
    m = red[0];
    #pragma unroll
    for (int i = 1; i < 8; i++) m = fmaxf(m, red[i]);
    __syncthreads();

    float e0 = expf(v.x - m), e1 = expf(v.y - m);
    float e2 = expf(v.z - m), e3 = expf(v.w - m);
    float s = e0 + e1 + e2 + e3;
    #pragma unroll
    for (int o = 16; o; o >>= 1) s += __shfl_xor_sync(0xffffffffu, s, o);
    if ((t & 31) == 0) red[t >> 5] = s;
    __syncthreads();
    s = red[0] + red[1] + red[2] + red[3] + red[4] + red[5] + red[6] + red[7];

    const float inv = 1.0f / s;
    const float w0 = e0 * inv, w1 = e1 * inv, w2 = e2 * inv, w3 = e3 * inv;
    w[t] = make_float4(w0, w1, w2, w3);

    hf h0 = __float2half_rn(w0), h1 = __float2half_rn(w1);
    hf h2 = __float2half_rn(w2), h3 = __float2half_rn(w3);
    hf l0 = __float2half_rn(w0 - __half2float(h0));
    hf l1 = __float2half_rn(w1 - __half2float(h1));
    hf l2 = __float2half_rn(w2 - __half2float(h2));
    hf l3 = __float2half_rn(w3 - __half2float(h3));
    ((uint2*)(Wh + (row << 10)))[t] = make_uint2(packh(h0, h1), packh(h2, h3));
    ((uint2*)(Wl + (row << 10)))[t] = make_uint2(packh(l0, l1), packh(l2, l3));
}

// -------------------------------- launcher ---------------------------------
extern "C" void kernel_launch(void* const* d_in, const int* in_sizes, int n_in,
                              void* d_out, int out_size)
{
    const float* hidden = (const float*)d_in[0];
    const float* enc    = (const float*)d_in[1];
    const float* Wa     = (const float*)d_in[2];
    const float* ba     = (const float*)d_in[3];
    const float* Wo     = (const float*)d_in[4];

    float* out = (float*)d_out;
    const long long SZ = (long long)NBT;
    float* htilde = out;
    float* wts    = out + SZ;
    float* enrg   = out + 2 * SZ;

    hf *enc_h, *enc_l, *encT_h, *encT_l, *hid_h, *hid_l, *proj_h, *proj_l;
    hf *wts_h, *wts_l, *ctx_h, *ctx_l, *wa_h, *wa_l, *wo_h, *wo_l;
    cudaGetSymbolAddress((void**)&enc_h,  g_enc_h);  cudaGetSymbolAddress((void**)&enc_l,  g_enc_l);
    cudaGetSymbolAddress((void**)&encT_h, g_encT_h); cudaGetSymbolAddress((void**)&encT_l, g_encT_l);
    cudaGetSymbolAddress((void**)&hid_h,  g_hid_h);  cudaGetSymbolAddress((void**)&hid_l,  g_hid_l);
    cudaGetSymbolAddress((void**)&proj_h, g_proj_h); cudaGetSymbolAddress((void**)&proj_l, g_proj_l);
    cudaGetSymbolAddress((void**)&wts_h,  g_wts_h);  cudaGetSymbolAddress((void**)&wts_l,  g_wts_l);
    cudaGetSymbolAddress((void**)&ctx_h,  g_ctx_h);  cudaGetSymbolAddress((void**)&ctx_l,  g_ctx_l);
    cudaGetSymbolAddress((void**)&wa_h,   g_wa_h);   cudaGetSymbolAddress((void**)&wa_l,   g_wa_l);
    cudaGetSymbolAddress((void**)&wo_h,   g_wo_h);   cudaGetSymbolAddress((void**)&wo_l,   g_wo_l);

    cudaFuncSetAttribute(mma_gemm<1, 3>, cudaFuncAttributeMaxDynamicSharedMemorySize, SMEM_BYTES);
    cudaFuncSetAttribute(mma_gemm<0, 3>, cudaFuncAttributeMaxDynamicSharedMemorySize, SMEM_BYTES);
    cudaFuncSetAttribute(mma_gemm<2, 2>, cudaFuncAttributeMaxDynamicSharedMemorySize, SMEM_BYTES);
    cudaFuncSetAttribute(mma_gemm<3, 2>, cudaFuncAttributeMaxDynamicSharedMemorySize, SMEM_BYTES);

    // operand splits
    split_k<<<NBT / 4 / 256, 256>>>((const float4*)enc,    (uint2*)enc_h, (uint2*)enc_l, NBT / 4);
    split_k<<<NBT / 4 / 256, 256>>>((const float4*)hidden, (uint2*)hid_h, (uint2*)hid_l, NBT / 4);
    split_k<<<1024, 256>>>((const float4*)Wa, (uint2*)wa_h, (uint2*)wa_l, 1024 * 1024 / 4);
    split_k<<<2048, 256>>>((const float4*)Wo, (uint2*)wo_h, (uint2*)wo_l, 1024 * 2048 / 4);
    tsplit_k<<<dim3(EDIM / 32, SDIM / 32, BATCH), 256>>>(enc, encT_h, encT_l);

    // Stage 1: proj = enc @ Wa^T + ba -> split  (3-term; feeds energies)
    mma_gemm<1, 3><<<dim3(DDIM / 128, (BATCH * SDIM) / 128, 1), 256, SMEM_BYTES>>>(
        enc_h, enc_l, wa_h, wa_l, nullptr, nullptr, nullptr, nullptr, ba,
        nullptr, proj_h, proj_l, EDIM / 64, 0, EDIM, EDIM, 0, 0, DDIM, 0, 0, 0);

    // Stage 2: energies = hidden @ proj^T (batched, 3-term) -> fp32
    mma_gemm<0, 3><<<dim3(SDIM / 128, TDIM / 128, BATCH), 256, SMEM_BYTES>>>(
        hid_h, hid_l, proj_h, proj_l, nullptr, nullptr, nullptr, nullptr, nullptr,
        enrg, nullptr, nullptr, DDIM / 64, 0, DDIM, DDIM, 0, 0, SDIM,
        (long long)TDIM * DDIM, (long long)SDIM * DDIM, (long long)TDIM * SDIM);

    // Stage 3: softmax -> fp32 weights + fp16 split
    softmax_sp<<<BATCH * TDIM, 256>>>(enrg, wts, wts_h, wts_l);

    // Stage 4: ctx = weights @ encT^T (batched, 2-term) -> split
    mma_gemm<2, 2><<<dim3(EDIM / 128, TDIM / 128, BATCH), 256, SMEM_BYTES>>>(
        wts_h, wts_l, encT_h, encT_l, nullptr, nullptr, nullptr, nullptr, nullptr,
        nullptr, ctx_h, ctx_l, SDIM / 64, 0, SDIM, SDIM, 0, 0, EDIM,
        (long long)TDIM * SDIM, (long long)EDIM * SDIM, (long long)TDIM * EDIM);

    // Stage 5: h_tilde = tanh(ctx @ Wo[:, :E]^T + hidden @ Wo[:, E:]^T)  (2-term)
    mma_gemm<3, 2><<<dim3(DDIM / 128, (BATCH * TDIM) / 128, 1), 256, SMEM_BYTES>>>(
        ctx_h, ctx_l, wo_h, wo_l, hid_h, hid_l, wo_h + EDIM, wo_l + EDIM, nullptr,
        htilde, nullptr, nullptr, EDIM / 64, DDIM / 64,
        EDIM, EDIM + DDIM, DDIM, EDIM + DDIM, DDIM, 0, 0, 0);
}